// round 12
// baseline (speedup 1.0000x reference)
#include <cuda_runtime.h>
#include <cuda_fp16.h>
#include <cuda.h>
#include <cstdint>
#include <cstddef>

#define DEV_INLINE __device__ __forceinline__

// ---------------- problem sizes ----------------
static constexpr int Bb = 4, Tt = 1024, Mtot = 4096, Hh = 2048, Vv = 32000;
static constexpr int M_TILE = 128;   // per CTA (cg2 pair covers 256)
static constexpr int N_TILE = 256;   // D columns per pair
static constexpr int K_CHUNK = 64;
static constexpr int NMT = Mtot / M_TILE;   // 32 m-tiles
static constexpr int NNT = Vv / N_TILE;     // 125 n-tiles
static constexpr int NKC = Hh / K_CHUNK;    // 32 k-chunks
static constexpr int NSTAGE = 4;
static constexpr int NPAIRS = (NMT / 2) * NNT;  // 2000 pair-tiles
static constexpr int NWORK = 74;                // persistent cg2 pairs (148 CTAs)
static constexpr int NCONVW = 2 * 2 * NWORK;    // converter warps total: 296

// ---------------- device scratch (static: no allocation APIs) ----------------
__device__ __half g_xh[(size_t)Mtot * Hh];       // fp16 activations
__device__ __half g_wh[(size_t)Vv * Hh];         // fp16 weights
__device__ float  g_partial[(size_t)NNT * Mtot]; // per n-tile partial sumexp
__device__ float  g_tok[Mtot];                   // selected-token logit
__device__ unsigned int g_xcnt;                  // x-convert completion counter
__device__ unsigned int g_wcnt[NNT];             // per-slab W-convert counters

// ---------------- PTX helpers ----------------
DEV_INLINE uint32_t smem_to_u32(const void* p) {
    uint32_t a;
    asm("{ .reg .u64 t; cvta.to.shared.u64 t, %1; cvt.u32.u64 %0, t; }" : "=r"(a) : "l"(p));
    return a;
}
DEV_INLINE uint32_t elect_one_pred() {
    uint32_t pred;
    asm volatile("{\n\t.reg .pred p;\n\telect.sync _|p, 0xFFFFFFFF;\n\tselp.b32 %0, 1, 0, p;\n\t}" : "=r"(pred));
    return pred;
}
DEV_INLINE uint32_t cluster_rank() {
    uint32_t r;
    asm("mov.u32 %0, %%cluster_ctarank;" : "=r"(r));
    return r;
}
#define MBARRIER_INIT(addr, cnt) \
    asm volatile("mbarrier.init.shared.b64 [%0], %1;" :: "r"((uint32_t)(addr)), "r"((uint32_t)(cnt)) : "memory")
#define MBARRIER_EXPECT_TX(addr, bytes) \
    asm volatile("mbarrier.arrive.expect_tx.shared.b64 _, [%0], %1;" :: "r"((uint32_t)(addr)), "r"((uint32_t)(bytes)) : "memory")

// Arrive at the LEADER CTA's mbarrier (clear peer bit 24).
#define MBARRIER_ARRIVE_LEADER(addr) \
    asm volatile("{\n\t.reg .b32 la;\n\tand.b32 la, %0, 0xFEFFFFFF;\n\t" \
                 "mbarrier.arrive.shared::cluster.b64 _, [la];\n\t}" \
                 :: "r"((uint32_t)(addr)) : "memory")

DEV_INLINE void mbar_wait(uint32_t addr, uint32_t parity) {
    asm volatile(
        "{\n\t.reg .pred P;\n\t"
        "WL_%=:\n\t"
        "mbarrier.try_wait.parity.acquire.cta.shared::cta.b64 P, [%0], %1, 0x989680;\n\t"
        "@P bra.uni WD_%=;\n\t"
        "bra.uni WL_%=;\n\t"
        "WD_%=:\n\t}"
        :: "r"(addr), "r"(parity) : "memory");
}

// Poll a gpu-scope release-published counter until it reaches target.
DEV_INLINE void wait_cnt(unsigned int* p, unsigned int target) {
    unsigned int v;
    for (;;) {
        asm volatile("ld.acquire.gpu.global.u32 %0, [%1];" : "=r"(v) : "l"(p) : "memory");
        if (v >= target) break;
        asm volatile("nanosleep.u32 128;");
    }
}

// cta_group::2 2D TMA: both CTAs execute; complete_tx targets the LEADER's barrier.
DEV_INLINE void tma2d_cg2(uint32_t dst, const CUtensorMap* map, int cx, int cy, uint32_t mbar) {
    asm volatile(
        "{\n\t.reg .b32 lb;\n\t"
        "and.b32 lb, %4, 0xFEFFFFFF;\n\t"
        "cp.async.bulk.tensor.2d.cta_group::2.shared::cluster.global.tile.mbarrier::complete_tx::bytes "
        "[%0], [%1, {%2, %3}], [lb];\n\t}"
        :: "r"(dst), "l"(map), "r"(cx), "r"(cy), "r"(mbar) : "memory");
}

#define TCGEN05_ALLOC_CG2(smem_addr, nCols) \
    asm volatile("tcgen05.alloc.cta_group::2.sync.aligned.shared::cta.b32 [%0], %1;" \
                 :: "r"((uint32_t)(smem_addr)), "r"((uint32_t)(nCols)) : "memory")
#define TCGEN05_RELINQ_CG2() \
    asm volatile("tcgen05.relinquish_alloc_permit.cta_group::2.sync.aligned;")
#define TCGEN05_DEALLOC_CG2(tmem_addr, nCols) \
    asm volatile("tcgen05.dealloc.cta_group::2.sync.aligned.b32 %0, %1;" :: "r"(tmem_addr), "r"((uint32_t)(nCols)))
#define TCGEN05_COMMIT_MC_CG2(mbar, mask) \
    asm volatile("tcgen05.commit.cta_group::2.mbarrier::arrive::one.shared::cluster.multicast::cluster.b64 [%0], %1;" \
                 :: "r"((uint32_t)(mbar)), "h"((uint16_t)(mask)) : "memory")
#define TCGEN05_WAIT_LD() asm volatile("tcgen05.wait::ld.sync.aligned;" ::: "memory")
#define TCGEN05_FENCE_AFTER() asm volatile("tcgen05.fence::after_thread_sync;" ::: "memory")
#define TCGEN05_FENCE_BEFORE() asm volatile("tcgen05.fence::before_thread_sync;" ::: "memory")
#define CLUSTER_SYNC() do { \
    asm volatile("barrier.cluster.arrive.aligned;" ::: "memory"); \
    asm volatile("barrier.cluster.wait.aligned;" ::: "memory"); \
} while (0)

#define TCGEN05_LD_X32(r, tmem_addr) \
    asm volatile( \
        "tcgen05.ld.sync.aligned.32x32b.x32.b32 " \
        "{%0, %1, %2, %3, %4, %5, %6, %7, " \
        " %8, %9, %10, %11, %12, %13, %14, %15, " \
        " %16, %17, %18, %19, %20, %21, %22, %23, " \
        " %24, %25, %26, %27, %28, %29, %30, %31}, [%32];" \
        : "=r"((r)[0]),  "=r"((r)[1]),  "=r"((r)[2]),  "=r"((r)[3]), \
          "=r"((r)[4]),  "=r"((r)[5]),  "=r"((r)[6]),  "=r"((r)[7]), \
          "=r"((r)[8]),  "=r"((r)[9]),  "=r"((r)[10]), "=r"((r)[11]), \
          "=r"((r)[12]), "=r"((r)[13]), "=r"((r)[14]), "=r"((r)[15]), \
          "=r"((r)[16]), "=r"((r)[17]), "=r"((r)[18]), "=r"((r)[19]), \
          "=r"((r)[20]), "=r"((r)[21]), "=r"((r)[22]), "=r"((r)[23]), \
          "=r"((r)[24]), "=r"((r)[25]), "=r"((r)[26]), "=r"((r)[27]), \
          "=r"((r)[28]), "=r"((r)[29]), "=r"((r)[30]), "=r"((r)[31]) \
        : "r"(tmem_addr))

// SW128 K-major smem descriptor (LBO=1, SBO=64, version=1, layout=SW128)
static constexpr uint64_t SMEM_DESC_BASE_SW128 =
    (uint64_t(2) << 61) | (uint64_t(1) << 46) | (uint64_t(64) << 32) | (uint64_t(1) << 16);
DEV_INLINE uint64_t make_desc(uint32_t addr) {
    return SMEM_DESC_BASE_SW128 | ((uint64_t)(addr >> 4) & 0x3FFF);
}

// SS fp16 MMA, cta_group::2 (M=256 across the pair), fp32 accumulate
DEV_INLINE void mma_f16_ss_cg2(uint32_t d, uint64_t ad, uint64_t bd, uint32_t idesc, uint32_t en) {
    asm volatile(
        "{\n\t.reg .pred p;\n\tsetp.ne.u32 p, %4, 0;\n\t"
        "tcgen05.mma.cta_group::2.kind::f16 [%0], %1, %2, %3, {%5, %5, %5, %5, %5, %5, %5, %5}, p;\n\t}"
        :: "r"(d), "l"(ad), "l"(bd), "r"(idesc), "r"(en), "r"(0u) : "memory");
}

// idesc: dtype F32 (bit4), a/b F16 (=0), N=256 -> 32<<17, M=256 -> 16<<24
static constexpr uint32_t MMA_IDESC = (1u << 4) | ((N_TILE / 8) << 17) | ((2 * M_TILE / 16) << 24);

// ---------------- smem layout for GEMM kernel ----------------
static constexpr int SM_TMEMPTR = 0;
static constexpr int SM_FULL = 8;     // full[s]  = 8  + s*8  (leader-owned in use)
static constexpr int SM_EMPTY = 40;   // empty[s] = 40 + s*8  (both CTAs)
static constexpr int SM_DREADY = 72;  // dready[b] = 72 + b*8 (both CTAs)
static constexpr int SM_DFREE = 88;   // dfree[b]  = 88 + b*8 (leader, count=2)
static constexpr int SM_A0 = 1024;
static constexpr int TILE_OP = M_TILE * 128;             // 16384 B per operand tile
static constexpr int OFF_A = 0;
static constexpr int OFF_B = TILE_OP;                    // 16384
static constexpr int STAGE_BYTES = 2 * TILE_OP;          // 32768 per CTA
static constexpr int PAIR_STAGE_TX = 2 * STAGE_BYTES;    // 65536 (both CTAs -> leader mbar)
static constexpr int SM_BIAS = SM_A0 + NSTAGE * STAGE_BYTES;      // 132096 (2 bufs x 1KB)
static constexpr int SMEM_TOTAL_GEMM = SM_BIAS + 2 * N_TILE * 4;  // 134144

// ---------------- kernel: persistent cg2 fp16 GEMM + fused convert + epilogue ----------------
// 74 persistent cg2 pairs (148 CTAs), 8 warps each:
//   warps 0-3: TMEM epilogue (exp-reduce), double-buffered as in R8
//   warp 4:    TMA producer (polls slab-ready flags before each n-tile)
//   warp 5:    MMA (leader rank only)
//   warps 6-7: fp32->fp16 converters: x first, then W in n-slab (g-major) order,
//              publishing completion via red.release counters.
__global__ void __launch_bounds__(256) __cluster_dims__(2, 1, 1) gemm_kernel(
    const __grid_constant__ CUtensorMap xmap,
    const __grid_constant__ CUtensorMap wmap,
    const float* __restrict__ gx,
    const float* __restrict__ gw,
    const float* __restrict__ bias,
    const int* __restrict__ tok_ids)
{
#if defined(__CUDA_ARCH_FEAT_SM103_ALL) || defined(__CUDA_ARCH_FEAT_SM100_ALL) || defined(__CUDA_ARCH_FEAT_SM101_ALL)
    extern __shared__ char smem[];
    uint32_t sb = smem_to_u32(smem);
    int tid = threadIdx.x, wid = tid >> 5, lid = tid & 31;
    uint32_t rank = cluster_rank();
    int pid = (int)(blockIdx.x >> 1);        // persistent pair id, 0..73

    if (tid == 0) {
        #pragma unroll
        for (int s = 0; s < NSTAGE; s++) {
            MBARRIER_INIT(sb + SM_FULL + s * 8, 1);
            MBARRIER_INIT(sb + SM_EMPTY + s * 8, 1);
        }
        MBARRIER_INIT(sb + SM_DREADY + 0, 1);
        MBARRIER_INIT(sb + SM_DREADY + 8, 1);
        MBARRIER_INIT(sb + SM_DFREE + 0, 2);
        MBARRIER_INIT(sb + SM_DFREE + 8, 2);
        asm volatile("fence.proxy.async.shared::cta;" ::: "memory");
    }
    if (wid == 0) { TCGEN05_ALLOC_CG2(sb + SM_TMEMPTR, 512); TCGEN05_RELINQ_CG2(); }
    __syncthreads();

    // All mbarriers + TMEM alloc visible cluster-wide before any cg2 TMA/commit.
    CLUSTER_SYNC();

    uint32_t tmem;
    asm volatile("ld.shared.b32 %0, [%1];" : "=r"(tmem) : "r"(sb + SM_TMEMPTR));

    if (wid >= 6) {
        // ---- converter warps: x fully, then W slab-by-slab in g order ----
        int cw = (int)blockIdx.x * 2 + (wid - 6);   // 0..295
        size_t tb = (size_t)cw * 32 + (size_t)lid;
        size_t ts = (size_t)NCONVW * 32;

        {   // x: 4096x2048 fp32 -> fp16 (half2 granularity)
            const float2* x2 = (const float2*)gx;
            __half2* xh2 = (__half2*)g_xh;
            size_t nx = (size_t)Mtot * Hh / 2;
            for (size_t i = tb; i < nx; i += ts) {
                float2 v = x2[i];
                xh2[i] = __floats2half2_rn(v.x, v.y);
            }
            __syncwarp();
            if (lid == 0)
                asm volatile("red.release.gpu.global.add.u32 [%0], 1;" :: "l"(&g_xcnt) : "memory");
        }
        {   // W: 125 slabs of 256 rows x 2048, in g order
            const float2* w2 = (const float2*)gw;
            __half2* wh2 = (__half2*)g_wh;
            const size_t slab = (size_t)N_TILE * Hh / 2;   // 262144 half2
            for (int g = 0; g < NNT; g++) {
                size_t base = (size_t)g * slab;
                for (size_t i = tb; i < slab; i += ts) {
                    float2 v = w2[base + i];
                    wh2[base + i] = __floats2half2_rn(v.x, v.y);
                }
                __syncwarp();
                if (lid == 0)
                    asm volatile("red.release.gpu.global.add.u32 [%0], 1;" :: "l"(&g_wcnt[g]) : "memory");
            }
        }
    } else if (wid == 4) {
        // ---- TMA producer (both ranks; each loads its own A + its W slice) ----
        if (elect_one_pred()) {
            wait_cnt(&g_xcnt, NCONVW);               // x converted
            int q = 0;
            for (int t = pid; t < NPAIRS; t += NWORK) {
                int mt = ((t & 15) << 1) + (int)rank;
                int nt = t >> 4;
                int wy = nt * N_TILE + (int)rank * (N_TILE / 2);
                wait_cnt(&g_wcnt[nt], NCONVW);       // slab nt converted
                asm volatile("fence.proxy.async;" ::: "memory");
                for (int i = 0; i < NKC; i++, q++) {
                    int s = q & (NSTAGE - 1);
                    int j = q >> 2;
                    mbar_wait(sb + SM_EMPTY + s * 8, 1 ^ (j & 1));
                    uint32_t fb = sb + SM_FULL + s * 8;
                    if (rank == 0) MBARRIER_EXPECT_TX(fb, PAIR_STAGE_TX);
                    uint32_t st = sb + SM_A0 + s * STAGE_BYTES;
                    int kx = i * K_CHUNK;
                    tma2d_cg2(st + OFF_A, &xmap, kx, mt * M_TILE, fb);
                    tma2d_cg2(st + OFF_B, &wmap, kx, wy, fb);
                }
            }
        }
    } else if (wid == 5) {
        // ---- MMA warp (leader rank only) ----
        if (rank == 0 && elect_one_pred()) {
            int q = 0, tl = 0;
            for (int t = pid; t < NPAIRS; t += NWORK, tl++) {
                int buf = tl & 1;
                int need = tl >> 1;   // required epilogue completions on this buffer
                if (need > 0) {
                    mbar_wait(sb + SM_DFREE + buf * 8, (need - 1) & 1);
                    TCGEN05_FENCE_AFTER();
                }
                uint32_t dptr = tmem + buf * N_TILE;
                for (int i = 0; i < NKC; i++, q++) {
                    int s = q & (NSTAGE - 1);
                    int j = q >> 2;
                    mbar_wait(sb + SM_FULL + s * 8, j & 1);
                    uint32_t st = sb + SM_A0 + s * STAGE_BYTES;
                    uint64_t ad = make_desc(st + OFF_A);
                    uint64_t bd = make_desc(st + OFF_B);
                    #pragma unroll
                    for (int k = 0; k < 4; k++) {
                        uint64_t o = (uint64_t)(k * 2);
                        mma_f16_ss_cg2(dptr, ad + o, bd + o, MMA_IDESC, (i | k) != 0);
                    }
                    TCGEN05_COMMIT_MC_CG2(sb + SM_EMPTY + s * 8, 0x3);
                }
                TCGEN05_COMMIT_MC_CG2(sb + SM_DREADY + buf * 8, 0x3);
            }
        }
    } else {
        // ---- epilogue warps 0-3 (both CTAs) ----
        int tl = 0;
        for (int t = pid; t < NPAIRS; t += NWORK, tl++) {
            int buf = tl & 1;
            int mt = ((t & 15) << 1) + (int)rank;
            int nt = t >> 4;
            float* bsh = (float*)(smem + SM_BIAS + buf * N_TILE * 4);
            bsh[tid] = bias[nt * N_TILE + tid];
            bsh[tid + 128] = bias[nt * N_TILE + 128 + tid];

            int row = mt * M_TILE + wid * 32 + lid;
            int tcol = tok_ids[row] - nt * N_TILE;

            asm volatile("bar.sync 1, 128;" ::: "memory");
            mbar_wait(sb + SM_DREADY + buf * 8, (tl >> 1) & 1);
            TCGEN05_FENCE_AFTER();

            uint32_t dptr = tmem + buf * N_TILE;
            float sum = 0.f, tokv = 0.f;
            for (int base = 0; base < N_TILE; base += 32) {
                uint32_t r[32];
                TCGEN05_LD_X32(r, dptr + base);
                TCGEN05_WAIT_LD();
                #pragma unroll
                for (int c = 0; c < 32; c++) {
                    float lg = __uint_as_float(r[c]) + bsh[base + c];
                    sum += __expf(lg);
                    if (base + c == tcol) tokv = lg;
                }
            }
            TCGEN05_FENCE_BEFORE();
            g_partial[(size_t)nt * Mtot + row] = sum;
            if (tcol >= 0 && tcol < N_TILE) g_tok[row] = tokv;

            asm volatile("bar.sync 1, 128;" ::: "memory");
            if (tid == 0) MBARRIER_ARRIVE_LEADER(sb + SM_DFREE + buf * 8);
        }
    }

    __syncthreads();
    CLUSTER_SYNC();                       // both CTAs done with TMEM before dealloc
    if (wid == 0) TCGEN05_DEALLOC_CG2(tmem, 512);
    CLUSTER_SYNC();                       // no early exit vs in-flight peer ops
#endif
}

// ---------------- finalize (lse, loss, metrics) ----------------
// attention_mask is a bool array coerced to int32 by the harness.
__global__ void finalize_kernel(const int* __restrict__ mask,
                                const float* __restrict__ adv,
                                const float* __restrict__ oldlp,
                                float* __restrict__ out, int out_size)
{
    int t = threadIdx.x;  // 1024 threads; thread t handles token t of each batch row
    __shared__ float red[32];

    float ptl_b[4], msk_b[4];
    float clip = 0.f, coef = 0.f, kl = 0.f;

    #pragma unroll
    for (int b = 0; b < 4; b++) {
        int m = b * 1024 + t;
        float s = 0.f;
        for (int n = 0; n < NNT; n++) s += g_partial[(size_t)n * Mtot + m];
        float lse = logf(s);
        bool mk = mask[m] != 0;
        float lp = mk ? (g_tok[m] - lse) : 1.0f;   // INVALID_LOGPROB = 1.0
        float diff = lp - oldlp[m];
        float c1 = expf(diff);
        float a = adv[b];
        float c2 = fminf(fmaxf(c1, 0.8f), 1.2f);
        float pt = -fminf(c1 * a, c2 * a);
        float mf = mk ? 1.f : 0.f;
        ptl_b[b] = pt * mf;
        msk_b[b] = mf;
        bool icl = ((c1 < 0.8f) && (a < 0.f)) || ((c1 > 1.2f) && (a > 0.f));
        clip += (icl ? 1.f : 0.f) * mf;
        coef += c1;
        kl += diff * diff;
    }

    auto bred = [&](float v) -> float {
        #pragma unroll
        for (int o = 16; o; o >>= 1) v += __shfl_xor_sync(0xffffffffu, v, o);
        if ((t & 31) == 0) red[t >> 5] = v;
        __syncthreads();
        float r = 0.f;
        if (t < 32) {
            r = red[t];
            #pragma unroll
            for (int o = 16; o; o >>= 1) r += __shfl_xor_sync(0xffffffffu, r, o);
        }
        __syncthreads();
        return r;
    };

    float Ps[4], Ms[4];
    #pragma unroll
    for (int b = 0; b < 4; b++) { Ps[b] = bred(ptl_b[b]); Ms[b] = bred(msk_b[b]); }
    float CS = bred(clip);
    float CO = bred(coef);
    float KL = bred(kl);

    if (t == 0) {
        float loss = 0.f;
        float msum = 0.f;
        #pragma unroll
        for (int b = 0; b < 4; b++) {
            loss += Ps[b] / fmaxf(Ms[b], 1.f);
            msum += Ms[b];
        }
        loss *= 0.25f;
        float clipf = CS / fmaxf(msum, 1.f);
        float meanc = CO / (4096.f * 4.f);
        float meank = 0.5f * KL / (4096.f * 4.f);
        if (out_size >= 5) {
            out[0] = loss; out[1] = clipf; out[2] = loss; out[3] = meanc; out[4] = meank;
        } else if (out_size == 4) {
            out[0] = clipf; out[1] = loss; out[2] = meanc; out[3] = meank;
        } else {
            out[0] = loss;
        }
    }
}

// ---------------- host side ----------------
typedef CUresult (*PFN_encodeTiled)(CUtensorMap*, CUtensorMapDataType, cuuint32_t, void*,
                                    const cuuint64_t*, const cuuint64_t*, const cuuint32_t*,
                                    const cuuint32_t*, CUtensorMapInterleave, CUtensorMapSwizzle,
                                    CUtensorMapL2promotion, CUtensorMapFloatOOBfill);

static PFN_encodeTiled get_encoder() {
    void* fn = nullptr;
    cudaDriverEntryPointQueryResult st;
#if CUDART_VERSION >= 12050
    cudaGetDriverEntryPointByVersion("cuTensorMapEncodeTiled", &fn, 12000, cudaEnableDefault, &st);
#else
    cudaGetDriverEntryPoint("cuTensorMapEncodeTiled", &fn, cudaEnableDefault, &st);
#endif
    return (PFN_encodeTiled)fn;
}

static void make_map(PFN_encodeTiled enc, CUtensorMap* map, void* base,
                     cuuint64_t rows, cuuint32_t box_rows) {
    cuuint64_t dims[2] = {(cuuint64_t)Hh, rows};
    cuuint64_t strd[1] = {(cuuint64_t)Hh * sizeof(__half)};
    cuuint32_t box[2] = {(cuuint32_t)K_CHUNK, box_rows};
    cuuint32_t es[2] = {1, 1};
    enc(map, CU_TENSOR_MAP_DATA_TYPE_FLOAT16, 2, base, dims, strd, box, es,
        CU_TENSOR_MAP_INTERLEAVE_NONE, CU_TENSOR_MAP_SWIZZLE_128B,
        CU_TENSOR_MAP_L2_PROMOTION_L2_128B, CU_TENSOR_MAP_FLOAT_OOB_FILL_NONE);
}

extern "C" void kernel_launch(void* const* d_in, const int* in_sizes, int n_in,
                              void* d_out, int out_size)
{
    const float* x = (const float*)d_in[0];
    const float* w = (const float*)d_in[1];
    const float* bias = (const float*)d_in[2];
    const int* tok = (const int*)d_in[3];
    const int* mask = (const int*)d_in[4];
    const float* adv = (const float*)d_in[5];
    const float* oldlp = (const float*)d_in[6];

    // Reset convert-progress counters every launch (graph-replay safe).
    void *xc_p = nullptr, *wc_p = nullptr;
    cudaGetSymbolAddress(&xc_p, g_xcnt);
    cudaGetSymbolAddress(&wc_p, g_wcnt);
    cudaMemsetAsync(xc_p, 0, sizeof(unsigned int));
    cudaMemsetAsync(wc_p, 0, NNT * sizeof(unsigned int));

    void *xh_p = nullptr, *wh_p = nullptr;
    cudaGetSymbolAddress(&xh_p, g_xh);
    cudaGetSymbolAddress(&wh_p, g_wh);

    PFN_encodeTiled enc = get_encoder();

    CUtensorMap xmap, wmap;
    make_map(enc, &xmap, xh_p, (cuuint64_t)Mtot, (cuuint32_t)M_TILE);
    // W boxes are N/2 slices (128 rows): cg2 B-split, one owner per W byte
    make_map(enc, &wmap, wh_p, (cuuint64_t)Vv, (cuuint32_t)(N_TILE / 2));

    cudaFuncSetAttribute(gemm_kernel, cudaFuncAttributeMaxDynamicSharedMemorySize, SMEM_TOTAL_GEMM);
    gemm_kernel<<<2 * NWORK, 256, SMEM_TOTAL_GEMM>>>(xmap, wmap, x, w, bias, tok);

    finalize_kernel<<<1, 1024>>>(mask, adv, oldlp, (float*)d_out, out_size);
}

// round 14
// speedup vs baseline: 1.6021x; 1.6021x over previous
#include <cuda_runtime.h>
#include <cuda_fp16.h>
#include <cuda.h>
#include <cstdint>
#include <cstddef>

#define DEV_INLINE __device__ __forceinline__

// ---------------- problem sizes ----------------
static constexpr int Bb = 4, Tt = 1024, Mtot = 4096, Hh = 2048, Vv = 32000;
static constexpr int M_TILE = 128;   // per CTA (cg2 pair covers 256)
static constexpr int N_TILE = 256;   // D columns per pair
static constexpr int K_CHUNK = 64;
static constexpr int NMT = Mtot / M_TILE;   // 32 m-tiles
static constexpr int NNT = Vv / N_TILE;     // 125 n-tiles
static constexpr int NKC = Hh / K_CHUNK;    // 32 k-chunks
static constexpr int NSTAGE = 4;
static constexpr int NPAIRS = (NMT / 2) * NNT;  // 2000 pair-tiles
static constexpr int NWORK = 74;                // persistent cg2 pairs (148 CTAs)

// ---------------- device scratch (static: no allocation APIs) ----------------
__device__ __half g_xh[(size_t)Mtot * Hh];       // fp16 activations
__device__ __half g_wh[(size_t)Vv * Hh];         // fp16 weights
__device__ float  g_partial[(size_t)NNT * Mtot]; // per n-tile partial sumexp
__device__ float  g_tok[Mtot];                   // selected-token logit
__device__ float  g_lse[Mtot];                   // per-row logsumexp

// ---------------- PTX helpers ----------------
DEV_INLINE uint32_t smem_to_u32(const void* p) {
    uint32_t a;
    asm("{ .reg .u64 t; cvta.to.shared.u64 t, %1; cvt.u32.u64 %0, t; }" : "=r"(a) : "l"(p));
    return a;
}
DEV_INLINE uint32_t elect_one_pred() {
    uint32_t pred;
    asm volatile("{\n\t.reg .pred p;\n\telect.sync _|p, 0xFFFFFFFF;\n\tselp.b32 %0, 1, 0, p;\n\t}" : "=r"(pred));
    return pred;
}
DEV_INLINE uint32_t cluster_rank() {
    uint32_t r;
    asm("mov.u32 %0, %%cluster_ctarank;" : "=r"(r));
    return r;
}
#define MBARRIER_INIT(addr, cnt) \
    asm volatile("mbarrier.init.shared.b64 [%0], %1;" :: "r"((uint32_t)(addr)), "r"((uint32_t)(cnt)) : "memory")
#define MBARRIER_EXPECT_TX(addr, bytes) \
    asm volatile("mbarrier.arrive.expect_tx.shared.b64 _, [%0], %1;" :: "r"((uint32_t)(addr)), "r"((uint32_t)(bytes)) : "memory")

// Arrive at the LEADER CTA's mbarrier (clear peer bit 24).
#define MBARRIER_ARRIVE_LEADER(addr) \
    asm volatile("{\n\t.reg .b32 la;\n\tand.b32 la, %0, 0xFEFFFFFF;\n\t" \
                 "mbarrier.arrive.shared::cluster.b64 _, [la];\n\t}" \
                 :: "r"((uint32_t)(addr)) : "memory")

DEV_INLINE void mbar_wait(uint32_t addr, uint32_t parity) {
    asm volatile(
        "{\n\t.reg .pred P;\n\t"
        "WL_%=:\n\t"
        "mbarrier.try_wait.parity.acquire.cta.shared::cta.b64 P, [%0], %1, 0x989680;\n\t"
        "@P bra.uni WD_%=;\n\t"
        "bra.uni WL_%=;\n\t"
        "WD_%=:\n\t}"
        :: "r"(addr), "r"(parity) : "memory");
}

// cta_group::2 2D TMA: both CTAs execute; complete_tx targets the LEADER's barrier.
DEV_INLINE void tma2d_cg2(uint32_t dst, const CUtensorMap* map, int cx, int cy, uint32_t mbar) {
    asm volatile(
        "{\n\t.reg .b32 lb;\n\t"
        "and.b32 lb, %4, 0xFEFFFFFF;\n\t"
        "cp.async.bulk.tensor.2d.cta_group::2.shared::cluster.global.tile.mbarrier::complete_tx::bytes "
        "[%0], [%1, {%2, %3}], [lb];\n\t}"
        :: "r"(dst), "l"(map), "r"(cx), "r"(cy), "r"(mbar) : "memory");
}

#define TCGEN05_ALLOC_CG2(smem_addr, nCols) \
    asm volatile("tcgen05.alloc.cta_group::2.sync.aligned.shared::cta.b32 [%0], %1;" \
                 :: "r"((uint32_t)(smem_addr)), "r"((uint32_t)(nCols)) : "memory")
#define TCGEN05_RELINQ_CG2() \
    asm volatile("tcgen05.relinquish_alloc_permit.cta_group::2.sync.aligned;")
#define TCGEN05_DEALLOC_CG2(tmem_addr, nCols) \
    asm volatile("tcgen05.dealloc.cta_group::2.sync.aligned.b32 %0, %1;" :: "r"(tmem_addr), "r"((uint32_t)(nCols)))
#define TCGEN05_COMMIT_MC_CG2(mbar, mask) \
    asm volatile("tcgen05.commit.cta_group::2.mbarrier::arrive::one.shared::cluster.multicast::cluster.b64 [%0], %1;" \
                 :: "r"((uint32_t)(mbar)), "h"((uint16_t)(mask)) : "memory")
#define TCGEN05_WAIT_LD() asm volatile("tcgen05.wait::ld.sync.aligned;" ::: "memory")
#define TCGEN05_FENCE_AFTER() asm volatile("tcgen05.fence::after_thread_sync;" ::: "memory")
#define TCGEN05_FENCE_BEFORE() asm volatile("tcgen05.fence::before_thread_sync;" ::: "memory")
#define CLUSTER_SYNC() do { \
    asm volatile("barrier.cluster.arrive.aligned;" ::: "memory"); \
    asm volatile("barrier.cluster.wait.aligned;" ::: "memory"); \
} while (0)

#define TCGEN05_LD_X32(r, tmem_addr) \
    asm volatile( \
        "tcgen05.ld.sync.aligned.32x32b.x32.b32 " \
        "{%0, %1, %2, %3, %4, %5, %6, %7, " \
        " %8, %9, %10, %11, %12, %13, %14, %15, " \
        " %16, %17, %18, %19, %20, %21, %22, %23, " \
        " %24, %25, %26, %27, %28, %29, %30, %31}, [%32];" \
        : "=r"((r)[0]),  "=r"((r)[1]),  "=r"((r)[2]),  "=r"((r)[3]), \
          "=r"((r)[4]),  "=r"((r)[5]),  "=r"((r)[6]),  "=r"((r)[7]), \
          "=r"((r)[8]),  "=r"((r)[9]),  "=r"((r)[10]), "=r"((r)[11]), \
          "=r"((r)[12]), "=r"((r)[13]), "=r"((r)[14]), "=r"((r)[15]), \
          "=r"((r)[16]), "=r"((r)[17]), "=r"((r)[18]), "=r"((r)[19]), \
          "=r"((r)[20]), "=r"((r)[21]), "=r"((r)[22]), "=r"((r)[23]), \
          "=r"((r)[24]), "=r"((r)[25]), "=r"((r)[26]), "=r"((r)[27]), \
          "=r"((r)[28]), "=r"((r)[29]), "=r"((r)[30]), "=r"((r)[31]) \
        : "r"(tmem_addr))

// SW128 K-major smem descriptor (LBO=1, SBO=64, version=1, layout=SW128)
static constexpr uint64_t SMEM_DESC_BASE_SW128 =
    (uint64_t(2) << 61) | (uint64_t(1) << 46) | (uint64_t(64) << 32) | (uint64_t(1) << 16);
DEV_INLINE uint64_t make_desc(uint32_t addr) {
    return SMEM_DESC_BASE_SW128 | ((uint64_t)(addr >> 4) & 0x3FFF);
}

// SS fp16 MMA, cta_group::2 (M=256 across the pair), fp32 accumulate
DEV_INLINE void mma_f16_ss_cg2(uint32_t d, uint64_t ad, uint64_t bd, uint32_t idesc, uint32_t en) {
    asm volatile(
        "{\n\t.reg .pred p;\n\tsetp.ne.u32 p, %4, 0;\n\t"
        "tcgen05.mma.cta_group::2.kind::f16 [%0], %1, %2, %3, {%5, %5, %5, %5, %5, %5, %5, %5}, p;\n\t}"
        :: "r"(d), "l"(ad), "l"(bd), "r"(idesc), "r"(en), "r"(0u) : "memory");
}

// idesc: dtype F32 (bit4), a/b F16 (=0), N=256 -> 32<<17, M=256 -> 16<<24
static constexpr uint32_t MMA_IDESC = (1u << 4) | ((N_TILE / 8) << 17) | ((2 * M_TILE / 16) << 24);

// ---------------- smem layout for GEMM kernel ----------------
static constexpr int SM_TMEMPTR = 0;
static constexpr int SM_FULL = 8;     // full[s]  = 8  + s*8  (leader-owned in use)
static constexpr int SM_EMPTY = 40;   // empty[s] = 40 + s*8  (both CTAs)
static constexpr int SM_DREADY = 72;  // dready[b] = 72 + b*8 (both CTAs)
static constexpr int SM_DFREE = 88;   // dfree[b]  = 88 + b*8 (leader, count=2)
static constexpr int SM_A0 = 1024;
static constexpr int TILE_OP = M_TILE * 128;             // 16384 B per operand tile
static constexpr int OFF_A = 0;
static constexpr int OFF_B = TILE_OP;                    // 16384
static constexpr int STAGE_BYTES = 2 * TILE_OP;          // 32768 per CTA
static constexpr int PAIR_STAGE_TX = 2 * STAGE_BYTES;    // 65536 (both CTAs -> leader mbar)
static constexpr int SM_BIAS = SM_A0 + NSTAGE * STAGE_BYTES;      // 132096 (2 bufs x 1KB)
static constexpr int SMEM_TOTAL_GEMM = SM_BIAS + 2 * N_TILE * 4;  // 134144

// ---------------- kernel 1: fp32 -> fp16 convert (float4 vectorized) ----------------
__global__ void convert_kernel(const float* __restrict__ x, const float* __restrict__ w) {
    size_t nw = (size_t)Vv * Hh / 4;
    size_t nx = (size_t)Mtot * Hh / 4;
    size_t stride = (size_t)gridDim.x * blockDim.x;
    size_t t0 = (size_t)blockIdx.x * blockDim.x + threadIdx.x;
    const float4* w4 = (const float4*)w;
    const float4* x4 = (const float4*)x;
    uint2* wh4 = (uint2*)g_wh;
    uint2* xh4 = (uint2*)g_xh;
    for (size_t i = t0; i < nw; i += stride) {
        float4 v = w4[i];
        __half2 lo = __floats2half2_rn(v.x, v.y);
        __half2 hi = __floats2half2_rn(v.z, v.w);
        uint2 o;
        o.x = *(uint32_t*)&lo;
        o.y = *(uint32_t*)&hi;
        wh4[i] = o;
    }
    for (size_t i = t0; i < nx; i += stride) {
        float4 v = x4[i];
        __half2 lo = __floats2half2_rn(v.x, v.y);
        __half2 hi = __floats2half2_rn(v.z, v.w);
        uint2 o;
        o.x = *(uint32_t*)&lo;
        o.y = *(uint32_t*)&hi;
        xh4[i] = o;
    }
}

// ---------------- kernel 2: persistent cg2 fp16 GEMM + overlapped epilogue ----------------
// (identical to the measured-best R8 pipeline)
__global__ void __launch_bounds__(192) __cluster_dims__(2, 1, 1) gemm_kernel(
    const __grid_constant__ CUtensorMap xmap,
    const __grid_constant__ CUtensorMap wmap,
    const float* __restrict__ bias,
    const int* __restrict__ tok_ids)
{
#if defined(__CUDA_ARCH_FEAT_SM103_ALL) || defined(__CUDA_ARCH_FEAT_SM100_ALL) || defined(__CUDA_ARCH_FEAT_SM101_ALL)
    extern __shared__ char smem[];
    uint32_t sb = smem_to_u32(smem);
    int tid = threadIdx.x, wid = tid >> 5, lid = tid & 31;
    uint32_t rank = cluster_rank();
    int pid = (int)(blockIdx.x >> 1);        // persistent pair id, 0..73

    if (tid == 0) {
        #pragma unroll
        for (int s = 0; s < NSTAGE; s++) {
            MBARRIER_INIT(sb + SM_FULL + s * 8, 1);
            MBARRIER_INIT(sb + SM_EMPTY + s * 8, 1);
        }
        MBARRIER_INIT(sb + SM_DREADY + 0, 1);
        MBARRIER_INIT(sb + SM_DREADY + 8, 1);
        MBARRIER_INIT(sb + SM_DFREE + 0, 2);
        MBARRIER_INIT(sb + SM_DFREE + 8, 2);
        asm volatile("fence.proxy.async.shared::cta;" ::: "memory");
    }
    if (wid == 0) { TCGEN05_ALLOC_CG2(sb + SM_TMEMPTR, 512); TCGEN05_RELINQ_CG2(); }
    __syncthreads();

    // All mbarriers + TMEM alloc visible cluster-wide before any cg2 TMA/commit.
    CLUSTER_SYNC();

    uint32_t tmem;
    asm volatile("ld.shared.b32 %0, [%1];" : "=r"(tmem) : "r"(sb + SM_TMEMPTR));

    if (wid == 4) {
        // ---- TMA producer (both ranks; each loads its own A + its W slice) ----
        if (elect_one_pred()) {
            int q = 0;                                    // global chunk counter
            for (int t = pid; t < NPAIRS; t += NWORK) {
                int mt = ((t & 15) << 1) + (int)rank;
                int nt = t >> 4;
                int wy = nt * N_TILE + (int)rank * (N_TILE / 2);
                for (int i = 0; i < NKC; i++, q++) {
                    int s = q & (NSTAGE - 1);
                    int j = q >> 2;
                    mbar_wait(sb + SM_EMPTY + s * 8, 1 ^ (j & 1));
                    uint32_t fb = sb + SM_FULL + s * 8;
                    if (rank == 0) MBARRIER_EXPECT_TX(fb, PAIR_STAGE_TX);
                    uint32_t st = sb + SM_A0 + s * STAGE_BYTES;
                    int kx = i * K_CHUNK;
                    tma2d_cg2(st + OFF_A, &xmap, kx, mt * M_TILE, fb);
                    tma2d_cg2(st + OFF_B, &wmap, kx, wy, fb);
                }
            }
        }
    } else if (wid == 5 && rank == 0) {
        // ---- MMA warp (leader only) ----
        if (elect_one_pred()) {
            int q = 0, tl = 0;
            for (int t = pid; t < NPAIRS; t += NWORK, tl++) {
                int buf = tl & 1;
                int need = tl >> 1;   // required epilogue completions on this buffer
                if (need > 0) {
                    mbar_wait(sb + SM_DFREE + buf * 8, (need - 1) & 1);
                    TCGEN05_FENCE_AFTER();
                }
                uint32_t dptr = tmem + buf * N_TILE;
                for (int i = 0; i < NKC; i++, q++) {
                    int s = q & (NSTAGE - 1);
                    int j = q >> 2;
                    mbar_wait(sb + SM_FULL + s * 8, j & 1);
                    uint32_t st = sb + SM_A0 + s * STAGE_BYTES;
                    uint64_t ad = make_desc(st + OFF_A);
                    uint64_t bd = make_desc(st + OFF_B);
                    #pragma unroll
                    for (int k = 0; k < 4; k++) {
                        uint64_t o = (uint64_t)(k * 2);
                        mma_f16_ss_cg2(dptr, ad + o, bd + o, MMA_IDESC, (i | k) != 0);
                    }
                    TCGEN05_COMMIT_MC_CG2(sb + SM_EMPTY + s * 8, 0x3);
                }
                TCGEN05_COMMIT_MC_CG2(sb + SM_DREADY + buf * 8, 0x3);
            }
        }
    } else if (wid < 4) {
        // ---- epilogue warps (both CTAs) ----
        int tl = 0;
        for (int t = pid; t < NPAIRS; t += NWORK, tl++) {
            int buf = tl & 1;
            int mt = ((t & 15) << 1) + (int)rank;
            int nt = t >> 4;
            float* bsh = (float*)(smem + SM_BIAS + buf * N_TILE * 4);
            bsh[tid] = bias[nt * N_TILE + tid];
            bsh[tid + 128] = bias[nt * N_TILE + 128 + tid];

            int row = mt * M_TILE + wid * 32 + lid;
            int tcol = tok_ids[row] - nt * N_TILE;

            asm volatile("bar.sync 1, 128;" ::: "memory");
            mbar_wait(sb + SM_DREADY + buf * 8, (tl >> 1) & 1);
            TCGEN05_FENCE_AFTER();

            uint32_t dptr = tmem + buf * N_TILE;
            float sum = 0.f, tokv = 0.f;
            for (int base = 0; base < N_TILE; base += 32) {
                uint32_t r[32];
                TCGEN05_LD_X32(r, dptr + base);
                TCGEN05_WAIT_LD();
                #pragma unroll
                for (int c = 0; c < 32; c++) {
                    float lg = __uint_as_float(r[c]) + bsh[base + c];
                    sum += __expf(lg);
                    if (base + c == tcol) tokv = lg;
                }
            }
            TCGEN05_FENCE_BEFORE();
            g_partial[(size_t)nt * Mtot + row] = sum;
            if (tcol >= 0 && tcol < N_TILE) g_tok[row] = tokv;

            asm volatile("bar.sync 1, 128;" ::: "memory");
            if (tid == 0) MBARRIER_ARRIVE_LEADER(sb + SM_DFREE + buf * 8);
        }
    }

    __syncthreads();
    CLUSTER_SYNC();                       // both CTAs done with TMEM before dealloc
    if (wid == 0) TCGEN05_DEALLOC_CG2(tmem, 512);
    CLUSTER_SYNC();                       // no early exit vs in-flight peer ops
#endif
}

// ---------------- kernel 3: parallel LSE reduction (125 partials -> logsumexp) ----------------
__global__ void lse_kernel() {
    int m = blockIdx.x * blockDim.x + threadIdx.x;   // 16 blocks x 256 = 4096 rows
    float s = 0.f;
    #pragma unroll 5
    for (int n = 0; n < NNT; n++) s += g_partial[(size_t)n * Mtot + m];
    g_lse[m] = logf(s);
}

// ---------------- kernel 4: finalize (loss, metrics) ----------------
// attention_mask is a bool array coerced to int32 by the harness.
__global__ void finalize_kernel(const int* __restrict__ mask,
                                const float* __restrict__ adv,
                                const float* __restrict__ oldlp,
                                float* __restrict__ out, int out_size)
{
    int t = threadIdx.x;  // 1024 threads; thread t handles token t of each batch row
    __shared__ float red[32];

    float ptl_b[4], msk_b[4];
    float clip = 0.f, coef = 0.f, kl = 0.f;

    #pragma unroll
    for (int b = 0; b < 4; b++) {
        int m = b * 1024 + t;
        float lse = g_lse[m];
        bool mk = mask[m] != 0;
        float lp = mk ? (g_tok[m] - lse) : 1.0f;   // INVALID_LOGPROB = 1.0
        float diff = lp - oldlp[m];
        float c1 = expf(diff);
        float a = adv[b];
        float c2 = fminf(fmaxf(c1, 0.8f), 1.2f);
        float pt = -fminf(c1 * a, c2 * a);
        float mf = mk ? 1.f : 0.f;
        ptl_b[b] = pt * mf;
        msk_b[b] = mf;
        bool icl = ((c1 < 0.8f) && (a < 0.f)) || ((c1 > 1.2f) && (a > 0.f));
        clip += (icl ? 1.f : 0.f) * mf;
        coef += c1;
        kl += diff * diff;
    }

    auto bred = [&](float v) -> float {
        #pragma unroll
        for (int o = 16; o; o >>= 1) v += __shfl_xor_sync(0xffffffffu, v, o);
        if ((t & 31) == 0) red[t >> 5] = v;
        __syncthreads();
        float r = 0.f;
        if (t < 32) {
            r = red[t];
            #pragma unroll
            for (int o = 16; o; o >>= 1) r += __shfl_xor_sync(0xffffffffu, r, o);
        }
        __syncthreads();
        return r;
    };

    float Ps[4], Ms[4];
    #pragma unroll
    for (int b = 0; b < 4; b++) { Ps[b] = bred(ptl_b[b]); Ms[b] = bred(msk_b[b]); }
    float CS = bred(clip);
    float CO = bred(coef);
    float KL = bred(kl);

    if (t == 0) {
        float loss = 0.f;
        float msum = 0.f;
        #pragma unroll
        for (int b = 0; b < 4; b++) {
            loss += Ps[b] / fmaxf(Ms[b], 1.f);
            msum += Ms[b];
        }
        loss *= 0.25f;
        float clipf = CS / fmaxf(msum, 1.f);
        float meanc = CO / (4096.f * 4.f);
        float meank = 0.5f * KL / (4096.f * 4.f);
        if (out_size >= 5) {
            out[0] = loss; out[1] = clipf; out[2] = loss; out[3] = meanc; out[4] = meank;
        } else if (out_size == 4) {
            out[0] = clipf; out[1] = loss; out[2] = meanc; out[3] = meank;
        } else {
            out[0] = loss;
        }
    }
}

// ---------------- host side ----------------
typedef CUresult (*PFN_encodeTiled)(CUtensorMap*, CUtensorMapDataType, cuuint32_t, void*,
                                    const cuuint64_t*, const cuuint64_t*, const cuuint32_t*,
                                    const cuuint32_t*, CUtensorMapInterleave, CUtensorMapSwizzle,
                                    CUtensorMapL2promotion, CUtensorMapFloatOOBfill);

static PFN_encodeTiled get_encoder() {
    void* fn = nullptr;
    cudaDriverEntryPointQueryResult st;
#if CUDART_VERSION >= 12050
    cudaGetDriverEntryPointByVersion("cuTensorMapEncodeTiled", &fn, 12000, cudaEnableDefault, &st);
#else
    cudaGetDriverEntryPoint("cuTensorMapEncodeTiled", &fn, cudaEnableDefault, &st);
#endif
    return (PFN_encodeTiled)fn;
}

static void make_map(PFN_encodeTiled enc, CUtensorMap* map, void* base,
                     cuuint64_t rows, cuuint32_t box_rows) {
    cuuint64_t dims[2] = {(cuuint64_t)Hh, rows};
    cuuint64_t strd[1] = {(cuuint64_t)Hh * sizeof(__half)};
    cuuint32_t box[2] = {(cuuint32_t)K_CHUNK, box_rows};
    cuuint32_t es[2] = {1, 1};
    enc(map, CU_TENSOR_MAP_DATA_TYPE_FLOAT16, 2, base, dims, strd, box, es,
        CU_TENSOR_MAP_INTERLEAVE_NONE, CU_TENSOR_MAP_SWIZZLE_128B,
        CU_TENSOR_MAP_L2_PROMOTION_L2_128B, CU_TENSOR_MAP_FLOAT_OOB_FILL_NONE);
}

extern "C" void kernel_launch(void* const* d_in, const int* in_sizes, int n_in,
                              void* d_out, int out_size)
{
    const float* x = (const float*)d_in[0];
    const float* w = (const float*)d_in[1];
    const float* bias = (const float*)d_in[2];
    const int* tok = (const int*)d_in[3];
    const int* mask = (const int*)d_in[4];
    const float* adv = (const float*)d_in[5];
    const float* oldlp = (const float*)d_in[6];

    convert_kernel<<<2048, 256>>>(x, w);

    void *xh_p = nullptr, *wh_p = nullptr;
    cudaGetSymbolAddress(&xh_p, g_xh);
    cudaGetSymbolAddress(&wh_p, g_wh);

    PFN_encodeTiled enc = get_encoder();

    CUtensorMap xmap, wmap;
    make_map(enc, &xmap, xh_p, (cuuint64_t)Mtot, (cuuint32_t)M_TILE);
    // W boxes are N/2 slices (128 rows): cg2 B-split, one owner per W byte
    make_map(enc, &wmap, wh_p, (cuuint64_t)Vv, (cuuint32_t)(N_TILE / 2));

    cudaFuncSetAttribute(gemm_kernel, cudaFuncAttributeMaxDynamicSharedMemorySize, SMEM_TOTAL_GEMM);
    gemm_kernel<<<2 * NWORK, 192, SMEM_TOTAL_GEMM>>>(xmap, wmap, bias, tok);

    lse_kernel<<<16, 256>>>();
    finalize_kernel<<<1, 1024>>>(mask, adv, oldlp, (float*)d_out, out_size);
}